// round 5
// baseline (speedup 1.0000x reference)
#include <cuda_runtime.h>
#include <cuda_bf16.h>
#include <cstdint>

// Problem constants
#define BB 32
#define HH 480
#define WW 864
#define HW (HH * WW)
#define KHALF 7
#define CHUNK 20
#define ROWS (CHUNK + 2 * KHALF)    // 34 halo rows
#define NCH (HH / CHUNK)            // 24
#define NBLK (NCH * BB)             // 768 blocks -> single wave at 8/SM
#define TPB 224                     // 7 warps
#define ACT 216                     // gather phase: 216 * 4 = 864 cols
#define NW 27                       // 864 / 32 mask words per row
#define SW 30                       // padded row stride for sB/sI

__device__ double   g_psum[NBLK];
__device__ int      g_pcnt[NBLK];
__device__ unsigned g_ticket = 0;

// 15-tap horizontal OR-dilation of a 32-col bit word with neighbors.
__device__ __forceinline__ unsigned dil15(unsigned L, unsigned C, unsigned R) {
    unsigned long long x = ((unsigned long long)C << 32) | (unsigned long long)L;
    x |= x << 1; x |= x << 2; x |= x << 4;          // bit m = OR of bits m-7..m
    unsigned long long y = ((unsigned long long)R << 32) | (unsigned long long)C;
    y |= y >> 1; y |= y >> 2; y |= y >> 4;          // bit m = OR of bits m..m+7
    return (unsigned)(x >> 32) | (unsigned)y;
}

__global__ __launch_bounds__(TPB, 8) void bl_fused(const float* __restrict__ logits,
                                                   const int*   __restrict__ labels,
                                                   float* __restrict__ out) {
    __shared__ unsigned sB[ROWS * SW];       // bit: label==1 (np==255); raw = class mask
    __shared__ unsigned sI[ROWS * SW];       // bit: label==255 (ignore)
    __shared__ unsigned dA[ROWS * NW];       // horiz-dilated "has np==0"
    __shared__ unsigned dB[ROWS * NW];       // horiz-dilated "has np==255"
    __shared__ unsigned vmask[CHUNK * NW];   // final valid mask per output row

    const int chunk = blockIdx.x;
    const int b     = blockIdx.y;
    const int h0    = chunk * CHUNK;
    const int t     = threadIdx.x;
    const int wid   = t >> 5, lane = t & 31;

    // ---- Phase 1: labels -> bit planes (warp ballots; 1 warp-task per word) ----
    for (int task = wid; task < ROWS * NW; task += TPB / 32) {
        const int r = task / NW, w = task - r * NW;
        const int gh = h0 - KHALF + r;
        unsigned bm = 0, im = 0;
        if ((unsigned)gh < (unsigned)HH) {
            const int l = __ldg(labels + ((size_t)b * HH + gh) * WW + (w << 5) + lane);
            bm = __ballot_sync(0xFFFFFFFFu, l == 1);
            im = __ballot_sync(0xFFFFFFFFu, l == 255);
        }
        if (lane == 0) { sB[r * SW + 1 + w] = bm; sI[r * SW + 1 + w] = im; }
    }
    __syncthreads();

    // ---- Phase 2: horizontal 15-tap dilation of A (=~B in-bounds) and B ----
    for (int task = t; task < ROWS * NW; task += TPB) {
        const int r = task / NW, w = task - r * NW;
        const int gh = h0 - KHALF + r;
        unsigned da = 0, db = 0;
        if ((unsigned)gh < (unsigned)HH) {
            const unsigned* row = sB + r * SW + 1;
            const unsigned Bc = row[w];
            const unsigned Bl = (w > 0)      ? row[w - 1] : 0u;
            const unsigned Br = (w < NW - 1) ? row[w + 1] : 0u;
            const unsigned Al = (w > 0)      ? ~Bl : 0u;
            const unsigned Ar = (w < NW - 1) ? ~Br : 0u;
            da = dil15(Al, ~Bc, Ar);
            db = dil15(Bl, Bc, Br);
        }
        dA[task] = da;
        dB[task] = db;
    }
    __syncthreads();

    // ---- Phase 3: vertical 15-tap OR + validity ----
    for (int task = t; task < CHUNK * NW; task += TPB) {
        const int i = task / NW, w = task - i * NW;
        unsigned oa = 0, ob = 0;
#pragma unroll
        for (int k = 0; k < 15; k++) {
            oa |= dA[(i + k) * NW + w];
            ob |= dB[(i + k) * NW + w];
        }
        vmask[task] = oa & ob & ~sI[(i + KHALF) * SW + 1 + w];
    }
    __syncthreads();

    // ---- Phase 4: fused NLL gather ----
    float lsum = 0.0f;
    int   lcnt = 0;
    if (t < ACT) {
        const int w     = t >> 3;            // mask word for cols 4t..4t+3
        const int shift = (t & 7) * 4;
        const float* __restrict__ lg0 = logits + (size_t)b * 2 * HW + 4 * t;
        const float* __restrict__ lg1 = lg0 + HW;

#pragma unroll 5
        for (int i = 0; i < CHUNK; i++) {
            const unsigned nv = (vmask[i * NW + w] >> shift) & 0xFu;
            const unsigned nc = (sB[(i + KHALF) * SW + 1 + w] >> shift) & 0xFu;
            const float4 v0 = *(const float4*)(lg0 + (h0 + i) * WW);
            const float4 v1 = *(const float4*)(lg1 + (h0 + i) * WW);
            if (nv & 1u) lsum += (nc & 1u) ? v1.x : v0.x;
            if (nv & 2u) lsum += (nc & 2u) ? v1.y : v0.y;
            if (nv & 4u) lsum += (nc & 4u) ? v1.z : v0.z;
            if (nv & 8u) lsum += (nc & 8u) ? v1.w : v0.w;
            lcnt += __popc(nv);
        }
    }

    // ---- Block + grid reduction (ticketed last-block finalize) ----
#pragma unroll
    for (int o = 16; o > 0; o >>= 1) {
        lsum += __shfl_down_sync(0xFFFFFFFFu, lsum, o);
        lcnt += __shfl_down_sync(0xFFFFFFFFu, lcnt, o);
    }
    __shared__ float ws[TPB / 32];
    __shared__ int   wc[TPB / 32];
    __shared__ bool  s_last;
    if (lane == 0) { ws[wid] = lsum; wc[wid] = lcnt; }
    __syncthreads();

    const int bid = b * NCH + chunk;
    if (t == 0) {
        double bs = 0.0; int bc = 0;
#pragma unroll
        for (int i = 0; i < TPB / 32; i++) { bs += (double)ws[i]; bc += wc[i]; }
        g_psum[bid] = bs;
        g_pcnt[bid] = bc;
        __threadfence();
        const unsigned r = atomicAdd(&g_ticket, 1u);
        s_last = (r == NBLK - 1);
    }
    __syncthreads();

    if (s_last) {
        double ds = 0.0; long long dc = 0;
        for (int i = t; i < NBLK; i += TPB) { ds += g_psum[i]; dc += g_pcnt[i]; }
#pragma unroll
        for (int o = 16; o > 0; o >>= 1) {
            ds += __shfl_down_sync(0xFFFFFFFFu, ds, o);
            dc += __shfl_down_sync(0xFFFFFFFFu, dc, o);
        }
        __shared__ double    fs[TPB / 32];
        __shared__ long long fc[TPB / 32];
        if (lane == 0) { fs[wid] = ds; fc[wid] = dc; }
        __syncthreads();
        if (t == 0) {
            double S = 0.0; long long C = 0;
#pragma unroll
            for (int i = 0; i < TPB / 32; i++) { S += fs[i]; C += fc[i]; }
            if (C < 1) C = 1;
            out[0] = (float)(-S / (double)C);
            g_ticket = 0;                     // reset for next graph replay
        }
    }
}

extern "C" void kernel_launch(void* const* d_in, const int* in_sizes, int n_in,
                              void* d_out, int out_size) {
    const float* logits = (const float*)d_in[0];
    const int*   labels = (const int*)d_in[1];
    float*       out    = (float*)d_out;

    bl_fused<<<dim3(NCH, BB), TPB>>>(logits, labels, out);
}

// round 6
// speedup vs baseline: 1.0389x; 1.0389x over previous
#include <cuda_runtime.h>
#include <cuda_bf16.h>
#include <cstdint>

// Problem constants
#define BB 32
#define HH 480
#define WW 864
#define HW (HH * WW)
#define KHALF 7
#define CHUNK 20
#define ROWS (CHUNK + 2 * KHALF)    // 34 halo rows
#define NCH (HH / CHUNK)            // 24
#define NBLK (NCH * BB)             // 768 blocks -> single wave at 6/SM
#define TPB 224                     // 7 warps
#define ACT 216                     // gather phase: 216 * 4 = 864 cols
#define NW 27                       // 864 / 32 mask words per row
#define SW 30                       // padded row stride for sB/sI
#define NTASK (ROWS * NW)           // 918 word tasks

__device__ double   g_psum[NBLK];
__device__ int      g_pcnt[NBLK];
__device__ unsigned g_ticket = 0;

// 15-tap horizontal OR-dilation of a 32-col bit word with neighbors.
__device__ __forceinline__ unsigned dil15(unsigned L, unsigned C, unsigned R) {
    unsigned long long x = ((unsigned long long)C << 32) | (unsigned long long)L;
    x |= x << 1; x |= x << 2; x |= x << 4;          // bit m = OR of bits m-7..m
    unsigned long long y = ((unsigned long long)R << 32) | (unsigned long long)C;
    y |= y >> 1; y |= y >> 2; y |= y >> 4;          // bit m = OR of bits m..m+7
    return (unsigned)(x >> 32) | (unsigned)y;
}

__global__ __launch_bounds__(TPB, 6) void bl_fused(const float* __restrict__ logits,
                                                   const int*   __restrict__ labels,
                                                   float* __restrict__ out) {
    __shared__ unsigned sB[ROWS * SW];       // bit: label==1 (np==255); raw = class mask
    __shared__ unsigned sI[ROWS * SW];       // bit: label==255 (ignore)
    __shared__ unsigned dA[ROWS * NW];       // horiz-dilated "has np==0"
    __shared__ unsigned dB[ROWS * NW];       // horiz-dilated "has np==255"
    __shared__ unsigned vmask[CHUNK * NW];   // final valid mask per output row

    const int chunk = blockIdx.x;
    const int b     = blockIdx.y;
    const int h0    = chunk * CHUNK;
    const int t     = threadIdx.x;
    const int wid   = t >> 5, lane = t & 31;

    const float* __restrict__ lg0 = logits + (size_t)b * 2 * HW + 4 * t;
    const float* __restrict__ lg1 = lg0 + HW;

    // Early logits preload (row h0) — overlaps DRAM latency with phases 1-3.
    float4 a0, a1;
    if (t < ACT) {
        a0 = *(const float4*)(lg0 + h0 * WW);
        a1 = *(const float4*)(lg1 + h0 * WW);
    }

    // ---- Phase 1: labels -> bit planes (warp ballots, 4 loads in flight) ----
#pragma unroll 4
    for (int task = wid; task < NTASK; task += TPB / 32) {
        const int r = task / NW, w = task - r * NW;
        const int gh = h0 - KHALF + r;
        unsigned bm = 0, im = 0;
        if ((unsigned)gh < (unsigned)HH) {
            const int l = __ldg(labels + ((size_t)b * HH + gh) * WW + (w << 5) + lane);
            bm = __ballot_sync(0xFFFFFFFFu, l == 1);
            im = __ballot_sync(0xFFFFFFFFu, l == 255);
        }
        if (lane == 0) { sB[r * SW + 1 + w] = bm; sI[r * SW + 1 + w] = im; }
    }
    __syncthreads();

    // ---- Phase 2: horizontal 15-tap dilation of A (=~B in-bounds) and B ----
#pragma unroll 2
    for (int task = t; task < NTASK; task += TPB) {
        const int r = task / NW, w = task - r * NW;
        const int gh = h0 - KHALF + r;
        unsigned da = 0, db = 0;
        if ((unsigned)gh < (unsigned)HH) {
            const unsigned* row = sB + r * SW + 1;
            const unsigned Bc = row[w];
            const unsigned Bl = (w > 0)      ? row[w - 1] : 0u;
            const unsigned Br = (w < NW - 1) ? row[w + 1] : 0u;
            const unsigned Al = (w > 0)      ? ~Bl : 0u;
            const unsigned Ar = (w < NW - 1) ? ~Br : 0u;
            da = dil15(Al, ~Bc, Ar);
            db = dil15(Bl, Bc, Br);
        }
        dA[task] = da;
        dB[task] = db;
    }
    __syncthreads();

    // ---- Phase 3: vertical 15-tap OR + validity ----
#pragma unroll 2
    for (int task = t; task < CHUNK * NW; task += TPB) {
        const int i = task / NW, w = task - i * NW;
        unsigned oa = 0, ob = 0;
#pragma unroll
        for (int k = 0; k < 15; k++) {
            oa |= dA[(i + k) * NW + w];
            ob |= dB[(i + k) * NW + w];
        }
        vmask[task] = oa & ob & ~sI[(i + KHALF) * SW + 1 + w];
    }
    __syncthreads();

    // ---- Phase 4: fused NLL gather with rolling 1-row prefetch ----
    float lsum = 0.0f;
    int   lcnt = 0;
    if (t < ACT) {
        const int w     = t >> 3;            // mask word for cols 4t..4t+3
        const int shift = (t & 7) * 4;

#pragma unroll 4
        for (int i = 0; i < CHUNK; i++) {
            float4 b0, b1;
            if (i + 1 < CHUNK) {
                b0 = *(const float4*)(lg0 + (h0 + i + 1) * WW);
                b1 = *(const float4*)(lg1 + (h0 + i + 1) * WW);
            }
            const unsigned nv = (vmask[i * NW + w] >> shift) & 0xFu;
            const unsigned nc = (sB[(i + KHALF) * SW + 1 + w] >> shift) & 0xFu;
            if (nv & 1u) lsum += (nc & 1u) ? a1.x : a0.x;
            if (nv & 2u) lsum += (nc & 2u) ? a1.y : a0.y;
            if (nv & 4u) lsum += (nc & 4u) ? a1.z : a0.z;
            if (nv & 8u) lsum += (nc & 8u) ? a1.w : a0.w;
            lcnt += __popc(nv);
            a0 = b0; a1 = b1;
        }
    }

    // ---- Block + grid reduction (ticketed last-block finalize) ----
#pragma unroll
    for (int o = 16; o > 0; o >>= 1) {
        lsum += __shfl_down_sync(0xFFFFFFFFu, lsum, o);
        lcnt += __shfl_down_sync(0xFFFFFFFFu, lcnt, o);
    }
    __shared__ float ws[TPB / 32];
    __shared__ int   wc[TPB / 32];
    __shared__ bool  s_last;
    if (lane == 0) { ws[wid] = lsum; wc[wid] = lcnt; }
    __syncthreads();

    const int bid = b * NCH + chunk;
    if (t == 0) {
        double bs = 0.0; int bc = 0;
#pragma unroll
        for (int i = 0; i < TPB / 32; i++) { bs += (double)ws[i]; bc += wc[i]; }
        g_psum[bid] = bs;
        g_pcnt[bid] = bc;
        __threadfence();
        const unsigned r = atomicAdd(&g_ticket, 1u);
        s_last = (r == NBLK - 1);
    }
    __syncthreads();

    if (s_last) {
        double ds = 0.0; long long dc = 0;
        for (int i = t; i < NBLK; i += TPB) { ds += g_psum[i]; dc += g_pcnt[i]; }
#pragma unroll
        for (int o = 16; o > 0; o >>= 1) {
            ds += __shfl_down_sync(0xFFFFFFFFu, ds, o);
            dc += __shfl_down_sync(0xFFFFFFFFu, dc, o);
        }
        __shared__ double    fs[TPB / 32];
        __shared__ long long fc[TPB / 32];
        if (lane == 0) { fs[wid] = ds; fc[wid] = dc; }
        __syncthreads();
        if (t == 0) {
            double S = 0.0; long long C = 0;
#pragma unroll
            for (int i = 0; i < TPB / 32; i++) { S += fs[i]; C += fc[i]; }
            if (C < 1) C = 1;
            out[0] = (float)(-S / (double)C);
            g_ticket = 0;                     // reset for next graph replay
        }
    }
}

extern "C" void kernel_launch(void* const* d_in, const int* in_sizes, int n_in,
                              void* d_out, int out_size) {
    const float* logits = (const float*)d_in[0];
    const int*   labels = (const int*)d_in[1];
    float*       out    = (float*)d_out;

    bl_fused<<<dim3(NCH, BB), TPB>>>(logits, labels, out);
}

// round 7
// speedup vs baseline: 1.5309x; 1.4736x over previous
#include <cuda_runtime.h>
#include <cuda_bf16.h>
#include <cstdint>

// Problem constants
#define BB 32
#define HH 480
#define WW 864
#define HW (HH * WW)
#define KHALF 7
#define CHUNK 32
#define ROWS (CHUNK + 2 * KHALF)    // 46 smem rows
#define NCH (HH / CHUNK)            // 15
#define NBLK (NCH * BB)             // 480 blocks -> single wave at 4/SM
#define TPB 224                     // 7 warps
#define ACT 216                     // 216 * 4 = 864 cols
#define SWORDS 224                  // words per smem code row (896 B stride)

__device__ double   g_psum[NBLK];
__device__ int      g_pcnt[NBLK];
__device__ unsigned g_ticket = 0;

// code byte: bits[0:2] presence (bit0: np==0, bit1: np==255); bits[2:4] own class
// (1 = cls0, 2 = cls1, 0 = ignore). Zero byte = neutral (halo / OOB).

__global__ __launch_bounds__(TPB, 4) void bl_fused(const float* __restrict__ logits,
                                                   const int*   __restrict__ labels,
                                                   float* __restrict__ out) {
    __shared__ unsigned s_w[ROWS * SWORDS];   // 41,216 B

    const int chunk = blockIdx.x;
    const int b     = blockIdx.y;
    const int h0    = chunk * CHUNK;
    const int t     = threadIdx.x;
    const int wid   = t >> 5, lane = t & 31;

    // Zero smem (halos + OOB rows rely on this)
    for (int i = t; i < ROWS * SWORDS; i += TPB) s_w[i] = 0u;
    __syncthreads();

    // Fill: labels -> packed code words (int4-coalesced, 4 loads in flight)
#pragma unroll 4
    for (int u = t; u < ROWS * 216; u += TPB) {
        const int r  = u / 216;
        const int j  = u - r * 216;
        const int gh = h0 - KHALF + r;
        if ((unsigned)gh < (unsigned)HH) {
            const int4 l4 = *(const int4*)(labels + ((size_t)b * HH + gh) * WW + 4 * j);
            unsigned c0 = (l4.x == 255) ? 1u : (l4.x ? 0x0Au : 0x05u);
            unsigned c1 = (l4.y == 255) ? 1u : (l4.y ? 0x0Au : 0x05u);
            unsigned c2 = (l4.z == 255) ? 1u : (l4.z ? 0x0Au : 0x05u);
            unsigned c3 = (l4.w == 255) ? 1u : (l4.w ? 0x0Au : 0x05u);
            s_w[r * SWORDS + 2 + j] = c0 | (c1 << 8) | (c2 << 16) | (c3 << 24);
        }
    }
    __syncthreads();

    float lsum = 0.0f;
    int   lcnt = 0;

    if (t < ACT) {
        // ---- Loop A: compute per-row (valid,class) nibbles into m[8] ----
        unsigned s0 = 0, s1 = 0, s2 = 0, s3 = 0;
        unsigned m[CHUNK / 4];                   // 8 bits/row: [0:4) valid, [4:8) class
#pragma unroll
        for (int i = 0; i < CHUNK / 4; i++) m[i] = 0u;

        // Warmup: fold smem rows 0..13 (global h0-7 .. h0+6)
#pragma unroll
        for (int r = 0; r < 2 * KHALF; r++) {
            const unsigned* sw = s_w + r * SWORDS + t;
            unsigned W0 = sw[0], W4 = sw[4];
            unsigned base = (sw[1] | sw[2] | sw[3]) & 0x03030303u;
            unsigned M0 = W0 & 0x03030303u, M4 = W4 & 0x03030303u;
            unsigned w0 = (M0 & 0xFFFFFF00u) | base;
            unsigned w1 = (M0 & 0xFFFF0000u) | base | (M4 & 0x000000FFu);
            unsigned w2 = (M0 & 0xFF000000u) | base | (M4 & 0x0000FFFFu);
            unsigned w3 =                      base | (M4 & 0x00FFFFFFu);
            w0 |= w0 >> 16; w0 |= w0 >> 8;
            w1 |= w1 >> 16; w1 |= w1 >> 8;
            w2 |= w2 >> 16; w2 |= w2 >> 8;
            w3 |= w3 >> 16; w3 |= w3 >> 8;
            s0 = (s0 << 2) | (w0 & 3u);
            s1 = (s1 << 2) | (w1 & 3u);
            s2 = (s2 << 2) | (w2 & 3u);
            s3 = (s3 << 2) | (w3 & 3u);
        }

#pragma unroll 8
        for (int i = 0; i < CHUNK; i++) {
            const int r = i + 2 * KHALF;
            const unsigned* sw = s_w + r * SWORDS + t;
            unsigned W0 = sw[0], W4 = sw[4];
            unsigned base = (sw[1] | sw[2] | sw[3]) & 0x03030303u;
            const unsigned wC = s_w[(i + KHALF) * SWORDS + t + 2]; // own row h0+i
            unsigned M0 = W0 & 0x03030303u, M4 = W4 & 0x03030303u;
            unsigned w0 = (M0 & 0xFFFFFF00u) | base;
            unsigned w1 = (M0 & 0xFFFF0000u) | base | (M4 & 0x000000FFu);
            unsigned w2 = (M0 & 0xFF000000u) | base | (M4 & 0x0000FFFFu);
            unsigned w3 =                      base | (M4 & 0x00FFFFFFu);
            w0 |= w0 >> 16; w0 |= w0 >> 8;
            w1 |= w1 >> 16; w1 |= w1 >> 8;
            w2 |= w2 >> 16; w2 |= w2 >> 8;
            w3 |= w3 >> 16; w3 |= w3 >> 8;

            s0 = ((s0 << 2) | (w0 & 3u)) & 0x3FFFFFFFu;
            s1 = ((s1 << 2) | (w1 & 3u)) & 0x3FFFFFFFu;
            s2 = ((s2 << 2) | (w2 & 3u)) & 0x3FFFFFFFu;
            s3 = ((s3 << 2) | (w3 & 3u)) & 0x3FFFFFFFu;

            unsigned nib = 0;
            {
                unsigned ob = (wC >> 2) & 3u;
                if ((s0 & 0x15555555u) && (s0 & 0x2AAAAAAAu) && ob) nib |= 1u;
            }
            {
                unsigned ob = (wC >> 10) & 3u;
                if ((s1 & 0x15555555u) && (s1 & 0x2AAAAAAAu) && ob) nib |= 2u;
            }
            {
                unsigned ob = (wC >> 18) & 3u;
                if ((s2 & 0x15555555u) && (s2 & 0x2AAAAAAAu) && ob) nib |= 4u;
            }
            {
                unsigned ob = (wC >> 26) & 3u;
                if ((s3 & 0x15555555u) && (s3 & 0x2AAAAAAAu) && ob) nib |= 8u;
            }
            // class nibble: bit3 of each code byte (own==2)
            const unsigned cls = ((wC >> 3) & 1u) | ((wC >> 10) & 2u) |
                                 ((wC >> 17) & 4u) | ((wC >> 24) & 8u);
            m[i >> 2] |= (nib | (cls << 4)) << ((i & 3) * 8);
        }

        // ---- Loop B: pure streaming gather (no serial deps -> max MLP) ----
        const float* __restrict__ lg0 = logits + (size_t)b * 2 * HW + (size_t)h0 * WW + 4 * t;
        const float* __restrict__ lg1 = lg0 + HW;

#pragma unroll 4
        for (int i = 0; i < CHUNK; i++) {
            const float4 v0 = *(const float4*)(lg0 + i * WW);
            const float4 v1 = *(const float4*)(lg1 + i * WW);
            const unsigned byte = m[i >> 2] >> ((i & 3) * 8);
            const unsigned nv = byte & 0xFu;
            const unsigned nc = (byte >> 4) & 0xFu;
            if (nv & 1u) lsum += (nc & 1u) ? v1.x : v0.x;
            if (nv & 2u) lsum += (nc & 2u) ? v1.y : v0.y;
            if (nv & 4u) lsum += (nc & 4u) ? v1.z : v0.z;
            if (nv & 8u) lsum += (nc & 8u) ? v1.w : v0.w;
            lcnt += __popc(nv);
        }
    }

    // ---- Block + grid reduction (ticketed last-block finalize) ----
#pragma unroll
    for (int o = 16; o > 0; o >>= 1) {
        lsum += __shfl_down_sync(0xFFFFFFFFu, lsum, o);
        lcnt += __shfl_down_sync(0xFFFFFFFFu, lcnt, o);
    }
    __shared__ float ws[TPB / 32];
    __shared__ int   wc[TPB / 32];
    __shared__ bool  s_last;
    if (lane == 0) { ws[wid] = lsum; wc[wid] = lcnt; }
    __syncthreads();

    const int bid = b * NCH + chunk;
    if (t == 0) {
        double bs = 0.0; int bc = 0;
#pragma unroll
        for (int i = 0; i < TPB / 32; i++) { bs += (double)ws[i]; bc += wc[i]; }
        g_psum[bid] = bs;
        g_pcnt[bid] = bc;
        __threadfence();
        const unsigned r = atomicAdd(&g_ticket, 1u);
        s_last = (r == NBLK - 1);
    }
    __syncthreads();

    if (s_last) {
        double ds = 0.0; long long dc = 0;
        for (int i = t; i < NBLK; i += TPB) { ds += g_psum[i]; dc += g_pcnt[i]; }
#pragma unroll
        for (int o = 16; o > 0; o >>= 1) {
            ds += __shfl_down_sync(0xFFFFFFFFu, ds, o);
            dc += __shfl_down_sync(0xFFFFFFFFu, dc, o);
        }
        __shared__ double    fs[TPB / 32];
        __shared__ long long fc[TPB / 32];
        if (lane == 0) { fs[wid] = ds; fc[wid] = dc; }
        __syncthreads();
        if (t == 0) {
            double S = 0.0; long long C = 0;
#pragma unroll
            for (int i = 0; i < TPB / 32; i++) { S += fs[i]; C += fc[i]; }
            if (C < 1) C = 1;
            out[0] = (float)(-S / (double)C);
            g_ticket = 0;                     // reset for next graph replay
        }
    }
}

extern "C" void kernel_launch(void* const* d_in, const int* in_sizes, int n_in,
                              void* d_out, int out_size) {
    const float* logits = (const float*)d_in[0];
    const int*   labels = (const int*)d_in[1];
    float*       out    = (float*)d_out;

    bl_fused<<<dim3(NCH, BB), TPB>>>(logits, labels, out);
}

// round 9
// speedup vs baseline: 2.4790x; 1.6194x over previous
#include <cuda_runtime.h>
#include <cuda_bf16.h>
#include <cstdint>

// Problem constants
#define BB 32
#define HH 480
#define WW 864
#define HW (HH * WW)
#define KHALF 7
#define CHUNK 24
#define ROWS (CHUNK + 2 * KHALF)    // 38 halo rows
#define NCH (HH / CHUNK)            // 20
#define NBLK (NCH * BB)             // 640 blocks, single wave at 5/SM
#define TPB 224                     // 7 warps
#define ACT 216                     // 216 * 4 = 864 cols in gather
#define NWRD 27                     // 864/32 mask words per row
#define SWB 112                     // byte-plane row stride (28 words, 4 pad bytes)
#define VS 29                       // vA/vB row stride in words (idx0 = left pad)

__device__ double   g_psum[NBLK];
__device__ int      g_pcnt[NBLK];
__device__ unsigned g_ticket = 0;

// 15-tap horizontal OR-dilation of a 32-col bit word with its neighbors.
__device__ __forceinline__ unsigned dil15(unsigned L, unsigned C, unsigned R) {
    unsigned long long x = ((unsigned long long)C << 32) | (unsigned long long)L;
    x |= x << 1; x |= x << 2; x |= x << 4;          // bit m = OR of bits m-7..m
    unsigned long long y = ((unsigned long long)R << 32) | (unsigned long long)C;
    y |= y >> 1; y |= y >> 2; y |= y >> 4;          // bit m = OR of bits m..m+7
    return (unsigned)(x >> 32) | (unsigned)y;
}

__global__ __launch_bounds__(TPB, 5) void bl_fused(const float* __restrict__ logits,
                                                   const int*   __restrict__ labels,
                                                   float* __restrict__ out) {
    // Bit planes (1 bit/px, byte-addressed): A = np==0, B = np==255, I = ignore.
    __shared__ unsigned char sA[ROWS * SWB];
    __shared__ unsigned char sB[ROWS * SWB];
    __shared__ unsigned char sI[ROWS * SWB];
    __shared__ unsigned vA[CHUNK * VS];      // vertical 15-OR of A
    __shared__ unsigned vB[CHUNK * VS];      // vertical 15-OR of B
    __shared__ unsigned vM[CHUNK * NWRD];    // final valid mask

    const int chunk = blockIdx.x;
    const int b     = blockIdx.y;
    const int h0    = chunk * CHUNK;
    const int t     = threadIdx.x;
    const int wid   = t >> 5, lane = t & 31;

    // ---- Phase 0: zero planes + vA/vB (halos, pads rely on this) ----
    for (int i = t; i < (ROWS * SWB) / 4; i += TPB) {
        ((unsigned*)sA)[i] = 0u; ((unsigned*)sB)[i] = 0u; ((unsigned*)sI)[i] = 0u;
    }
    for (int i = t; i < CHUNK * VS; i += TPB) { vA[i] = 0u; vB[i] = 0u; }
    __syncthreads();

    // ---- Phase 1: ingest labels -> bit planes (8 px/thread, coalesced) ----
#pragma unroll 4
    for (int u = t; u < ROWS * 108; u += TPB) {
        const int r  = u / 108;
        const int j  = u - r * 108;            // byte index: cols 8j..8j+7
        const int gh = h0 - KHALF + r;
        if ((unsigned)gh < (unsigned)HH) {
            const int4* p = (const int4*)(labels + (size_t)((size_t)b * HH + gh) * WW + (size_t)8 * j);
            const int4 x = p[0];
            const int4 y = p[1];
            // labels in {0,1,255}: isB = (l ^ (l>>7)) & 1 ; isI = (l>>7) & 1
            unsigned bBv = ((unsigned)((x.x ^ (x.x >> 7)) & 1))
                         | ((unsigned)((x.y ^ (x.y >> 7)) & 1) << 1)
                         | ((unsigned)((x.z ^ (x.z >> 7)) & 1) << 2)
                         | ((unsigned)((x.w ^ (x.w >> 7)) & 1) << 3)
                         | ((unsigned)((y.x ^ (y.x >> 7)) & 1) << 4)
                         | ((unsigned)((y.y ^ (y.y >> 7)) & 1) << 5)
                         | ((unsigned)((y.z ^ (y.z >> 7)) & 1) << 6)
                         | ((unsigned)((y.w ^ (y.w >> 7)) & 1) << 7);
            unsigned bIv = ((unsigned)((x.x >> 7) & 1))
                         | ((unsigned)((x.y >> 7) & 1) << 1)
                         | ((unsigned)((x.z >> 7) & 1) << 2)
                         | ((unsigned)((x.w >> 7) & 1) << 3)
                         | ((unsigned)((y.x >> 7) & 1) << 4)
                         | ((unsigned)((y.y >> 7) & 1) << 5)
                         | ((unsigned)((y.z >> 7) & 1) << 6)
                         | ((unsigned)((y.w >> 7) & 1) << 7);
            sB[r * SWB + j] = (unsigned char)bBv;
            sI[r * SWB + j] = (unsigned char)bIv;
            sA[r * SWB + j] = (unsigned char)(bBv ^ 0xFFu);   // A = ~B in-bounds
        }
    }
    __syncthreads();

    // ---- Phase 2: vertical 15-row OR per (output row, word) — 3 tasks/thread ----
#pragma unroll
    for (int q = 0; q < 3; q++) {
        const int u = t + q * TPB;              // CHUNK*28 = 672 = 3*TPB exactly
        const int i = u / 28, w = u - i * 28;   // w = 0..27 (27 = pad word)
        const unsigned char* pa = sA + i * SWB + 4 * w;
        const unsigned char* pb = sB + i * SWB + 4 * w;
        unsigned oa = 0, ob = 0;
#pragma unroll
        for (int k = 0; k < 15; k++) {
            oa |= *(const unsigned*)(pa + k * SWB);
            ob |= *(const unsigned*)(pb + k * SWB);
        }
        vA[i * VS + 1 + w] = oa;
        vB[i * VS + 1 + w] = ob;
    }
    __syncthreads();

    // ---- Phase 3: horizontal dil15 + validity ----
#pragma unroll 3
    for (int u = t; u < CHUNK * NWRD; u += TPB) {
        const int i = u / NWRD, w = u - i * NWRD;
        const unsigned* va = vA + i * VS + 1 + w;
        const unsigned* vb = vB + i * VS + 1 + w;
        const unsigned da = dil15(va[-1], va[0], va[1]);
        const unsigned db = dil15(vb[-1], vb[0], vb[1]);
        const unsigned Ic = *(const unsigned*)(sI + (i + KHALF) * SWB + 4 * w);
        vM[u] = da & db & ~Ic;
    }
    __syncthreads();

    // ---- Phase 4: streaming NLL gather ----
    float lsum = 0.0f;
    int   lcnt = 0;
    if (t < ACT) {
        const int w  = t >> 3;
        const int sh = (t & 7) * 4;
        const float* __restrict__ lg0 = logits + (size_t)b * 2 * HW + (size_t)h0 * WW + 4 * t;
        const float* __restrict__ lg1 = lg0 + HW;

#pragma unroll 6
        for (int i = 0; i < CHUNK; i++) {
            const unsigned nv = (vM[i * NWRD + w] >> sh) & 0xFu;
            const unsigned nc = ((*(const unsigned*)(sB + (i + KHALF) * SWB + 4 * w)) >> sh) & 0xFu;
            const float4 v0 = *(const float4*)(lg0 + i * WW);
            const float4 v1 = *(const float4*)(lg1 + i * WW);
            if (nv & 1u) lsum += (nc & 1u) ? v1.x : v0.x;
            if (nv & 2u) lsum += (nc & 2u) ? v1.y : v0.y;
            if (nv & 4u) lsum += (nc & 4u) ? v1.z : v0.z;
            if (nv & 8u) lsum += (nc & 8u) ? v1.w : v0.w;
            lcnt += __popc(nv);
        }
    }

    // ---- Block + grid reduction (ticketed last-block finalize) ----
#pragma unroll
    for (int o = 16; o > 0; o >>= 1) {
        lsum += __shfl_down_sync(0xFFFFFFFFu, lsum, o);
        lcnt += __shfl_down_sync(0xFFFFFFFFu, lcnt, o);
    }
    __shared__ float ws[TPB / 32];
    __shared__ int   wc[TPB / 32];
    __shared__ bool  s_last;
    if (lane == 0) { ws[wid] = lsum; wc[wid] = lcnt; }
    __syncthreads();

    const int bid = b * NCH + chunk;
    if (t == 0) {
        double bs = 0.0; int bc = 0;
#pragma unroll
        for (int i = 0; i < TPB / 32; i++) { bs += (double)ws[i]; bc += wc[i]; }
        g_psum[bid] = bs;
        g_pcnt[bid] = bc;
        __threadfence();
        const unsigned r = atomicAdd(&g_ticket, 1u);
        s_last = (r == NBLK - 1);
    }
    __syncthreads();

    if (s_last) {
        double ds = 0.0; long long dc = 0;
        for (int i = t; i < NBLK; i += TPB) { ds += g_psum[i]; dc += g_pcnt[i]; }
#pragma unroll
        for (int o = 16; o > 0; o >>= 1) {
            ds += __shfl_down_sync(0xFFFFFFFFu, ds, o);
            dc += __shfl_down_sync(0xFFFFFFFFu, dc, o);
        }
        __shared__ double    fs[TPB / 32];
        __shared__ long long fc[TPB / 32];
        if (lane == 0) { fs[wid] = ds; fc[wid] = dc; }
        __syncthreads();
        if (t == 0) {
            double S = 0.0; long long C = 0;
#pragma unroll
            for (int i = 0; i < TPB / 32; i++) { S += fs[i]; C += fc[i]; }
            if (C < 1) C = 1;
            out[0] = (float)(-S / (double)C);
            g_ticket = 0;                     // reset for next graph replay
        }
    }
}

extern "C" void kernel_launch(void* const* d_in, const int* in_sizes, int n_in,
                              void* d_out, int out_size) {
    const float* logits = (const float*)d_in[0];
    const int*   labels = (const int*)d_in[1];
    float*       out    = (float*)d_out;

    bl_fused<<<dim3(NCH, BB), TPB>>>(logits, labels, out);
}